// round 2
// baseline (speedup 1.0000x reference)
#include <cuda_runtime.h>
#include <math.h>
#include <stdint.h>

#define NN  50000
#define FINF 64
#define HH  128
#define EE  800000
#define TT  8
#define PP  250000
#define DD  500000
#define GG  20000
#define VV  2000
#define CATW 384

// ---------------- scratch (device globals; no allocation allowed) ----------------
__device__ __align__(16) float  g_feats[(size_t)(TT + 1) * NN * HH];
__device__ __align__(16) float  g_agg[(size_t)NN * HH];
__device__ __align__(16) float  g_cat[(size_t)PP * CATW];
__device__ __align__(16) float  g_hidden[(size_t)PP * CATW];
__device__ float  g_logprob[PP * 2];
__device__ double g_gsum[GG * 2];
__device__ float  g_within[GG * 2];
__device__ int    g_deg[NN];
__device__ float  g_invdeg[NN];
__device__ int    g_rowptr[NN + 1];
__device__ int    g_cursor[NN];
__device__ int    g_csr[EE];
__device__ int    g_vstart[VV];
__device__ float  g_logc[VV];

// ---------------- CSR build ----------------
__global__ void k_count_deg(const int* __restrict__ edge_dst) {
    int e = blockIdx.x * blockDim.x + threadIdx.x;
    if (e < EE) atomicAdd(&g_deg[edge_dst[e]], 1);
}

__global__ void k_scan() {
    __shared__ int warpsum[32];
    __shared__ int s_carry;
    if (threadIdx.x == 0) s_carry = 0;
    __syncthreads();
    int lane = threadIdx.x & 31, w = threadIdx.x >> 5;
    for (int base = 0; base < NN; base += 1024) {
        int i = base + threadIdx.x;
        int v = (i < NN) ? g_deg[i] : 0;
        int s = v;
#pragma unroll
        for (int o = 1; o < 32; o <<= 1) {
            int t = __shfl_up_sync(0xffffffffu, s, o);
            if (lane >= o) s += t;
        }
        if (lane == 31) warpsum[w] = s;
        __syncthreads();
        if (w == 0) {
            int ws = warpsum[lane];
#pragma unroll
            for (int o = 1; o < 32; o <<= 1) {
                int t = __shfl_up_sync(0xffffffffu, ws, o);
                if (lane >= o) ws += t;
            }
            warpsum[lane] = ws;
        }
        __syncthreads();
        int incl = s + (w > 0 ? warpsum[w - 1] : 0) + s_carry;
        if (i < NN) {
            g_rowptr[i + 1] = incl;
            g_cursor[i] = incl - v;
            g_invdeg[i] = 1.0f / (float)(v > 1 ? v : 1);
            if (i == 0) g_rowptr[0] = 0;
        }
        __syncthreads();
        if (threadIdx.x == 1023) s_carry = incl;
        __syncthreads();
    }
}

__global__ void k_fill(const int* __restrict__ edge_src, const int* __restrict__ edge_dst) {
    int e = blockIdx.x * blockDim.x + threadIdx.x;
    if (e >= EE) return;
    int pos = atomicAdd(&g_cursor[edge_dst[e]], 1);
    g_csr[pos] = edge_src[e];
}

// ---------------- mean aggregation (atomic-free via CSR) ----------------
template <int F>
__global__ void k_aggregate(const float* __restrict__ h) {
    int node = blockIdx.x * blockDim.y + threadIdx.y;
    if (node >= NN) return;
    int f = threadIdx.x;
    int e0 = g_rowptr[node], e1 = g_rowptr[node + 1];
    float s = 0.f;
    for (int e = e0; e < e1; e++) {
        int src = g_csr[e];
        s += h[(size_t)src * F + f];
    }
    g_agg[(size_t)node * F + f] = s * g_invdeg[node];
}

// ---------------- tensor-core GEMM (3xTF32 split precision) ----------------
// C = act(A1@W1 [+ A2@W2] + bias), BM=BN=128, BK=16, 256 threads (8 warps).
// Warp layout: 4 (m) x 2 (n), warp tile 32x64, mma.sync.m16n8k8 tf32.
#define BKP 20   // As row stride in words (BK=16 + 4 pad -> conflict-free frags)
#define BNP 136  // Bs row stride in words (BN=128 + 8 pad)

__device__ __forceinline__ uint32_t f2tf32(float v) {
    uint32_t r;
    asm("cvt.rna.tf32.f32 %0, %1;" : "=r"(r) : "f"(v));
    return r;
}

__device__ __forceinline__ void mma_tf32(float* c, const uint32_t* a, const uint32_t* b) {
    asm("mma.sync.aligned.m16n8k8.row.col.f32.tf32.tf32.f32 "
        "{%0,%1,%2,%3}, {%4,%5,%6,%7}, {%8,%9}, {%0,%1,%2,%3};"
        : "+f"(c[0]), "+f"(c[1]), "+f"(c[2]), "+f"(c[3])
        : "r"(a[0]), "r"(a[1]), "r"(a[2]), "r"(a[3]), "r"(b[0]), "r"(b[1]));
}

__global__ __launch_bounds__(256) void k_gemm_tc(
    const float* __restrict__ A1, int K1,
    const float* __restrict__ A2, int K2,
    const float* __restrict__ W1, const float* __restrict__ W2,
    const float* __restrict__ bias,
    float* __restrict__ C, int M, int NC, int doRelu)
{
    __shared__ uint32_t AsH[128 * BKP];
    __shared__ uint32_t AsL[128 * BKP];
    __shared__ uint32_t BsH[16 * BNP];
    __shared__ uint32_t BsL[16 * BNP];

    int tid = threadIdx.x;
    int wid = tid >> 5, lane = tid & 31;
    int gID = lane >> 2, tig = lane & 3;
    int wm = wid & 3, wn = wid >> 2;
    int rowBlock = blockIdx.y * 128, colBlock = blockIdx.x * 128;

    float acc[2][8][4];
#pragma unroll
    for (int a = 0; a < 2; a++)
#pragma unroll
        for (int b = 0; b < 8; b++)
#pragma unroll
            for (int c = 0; c < 4; c++) acc[a][b][c] = 0.f;

#pragma unroll 1
    for (int pass = 0; pass < 2; pass++) {
        const float* A = pass ? A2 : A1;
        const float* W = pass ? W2 : W1;
        int K = pass ? K2 : K1;
        if (A == nullptr) continue;
#pragma unroll 1
        for (int k0 = 0; k0 < K; k0 += 16) {
            // load + split A tile: 128x16 floats, 2 float4 per thread
#pragma unroll
            for (int i = 0; i < 2; i++) {
                int id = tid * 2 + i;
                int row = id >> 2, kk = (id & 3) * 4;
                int gm = rowBlock + row;
                float4 v = make_float4(0.f, 0.f, 0.f, 0.f);
                if (gm < M) v = *(const float4*)(A + (size_t)gm * K + k0 + kk);
                int base = row * BKP + kk;
                float vv[4] = {v.x, v.y, v.z, v.w};
#pragma unroll
                for (int j = 0; j < 4; j++) {
                    uint32_t h = f2tf32(vv[j]);
                    AsH[base + j] = h;
                    AsL[base + j] = f2tf32(vv[j] - __uint_as_float(h));
                }
            }
            // load + split B tile: 16x128 floats
#pragma unroll
            for (int i = 0; i < 2; i++) {
                int id = tid * 2 + i;
                int r = id >> 5, cc = (id & 31) * 4;
                float4 v = *(const float4*)(W + (size_t)(k0 + r) * NC + colBlock + cc);
                int base = r * BNP + cc;
                float vv[4] = {v.x, v.y, v.z, v.w};
#pragma unroll
                for (int j = 0; j < 4; j++) {
                    uint32_t h = f2tf32(vv[j]);
                    BsH[base + j] = h;
                    BsL[base + j] = f2tf32(vv[j] - __uint_as_float(h));
                }
            }
            __syncthreads();
#pragma unroll
            for (int ks = 0; ks < 2; ks++) {
                int kk = ks * 8;
                uint32_t aH[2][4], aL[2][4];
#pragma unroll
                for (int mt = 0; mt < 2; mt++) {
                    int r0 = wm * 32 + mt * 16 + gID;
                    int b = r0 * BKP + kk + tig;
                    aH[mt][0] = AsH[b];
                    aH[mt][1] = AsH[b + 8 * BKP];
                    aH[mt][2] = AsH[b + 4];
                    aH[mt][3] = AsH[b + 8 * BKP + 4];
                    aL[mt][0] = AsL[b];
                    aL[mt][1] = AsL[b + 8 * BKP];
                    aL[mt][2] = AsL[b + 4];
                    aL[mt][3] = AsL[b + 8 * BKP + 4];
                }
#pragma unroll
                for (int nt = 0; nt < 8; nt++) {
                    int c = wn * 64 + nt * 8 + gID;
                    int b0 = (kk + tig) * BNP + c;
                    int b1 = (kk + tig + 4) * BNP + c;
                    uint32_t bH[2] = {BsH[b0], BsH[b1]};
                    uint32_t bL[2] = {BsL[b0], BsL[b1]};
#pragma unroll
                    for (int mt = 0; mt < 2; mt++) {
                        mma_tf32(acc[mt][nt], aH[mt], bH);
                        mma_tf32(acc[mt][nt], aH[mt], bL);
                        mma_tf32(acc[mt][nt], aL[mt], bH);
                    }
                }
            }
            __syncthreads();
        }
    }

    // epilogue: bias + optional relu
#pragma unroll
    for (int mt = 0; mt < 2; mt++) {
        int r0 = rowBlock + wm * 32 + mt * 16 + gID;
#pragma unroll
        for (int nt = 0; nt < 8; nt++) {
            int col = colBlock + wn * 64 + nt * 8 + tig * 2;
            float bb0 = bias[col], bb1 = bias[col + 1];
            float v0 = acc[mt][nt][0] + bb0;
            float v1 = acc[mt][nt][1] + bb1;
            float v2 = acc[mt][nt][2] + bb0;
            float v3 = acc[mt][nt][3] + bb1;
            if (doRelu) {
                v0 = fmaxf(v0, 0.f); v1 = fmaxf(v1, 0.f);
                v2 = fmaxf(v2, 0.f); v3 = fmaxf(v3, 0.f);
            }
            if (r0 < M)     *(float2*)(C + (size_t)r0 * NC + col)       = make_float2(v0, v1);
            if (r0 + 8 < M) *(float2*)(C + (size_t)(r0 + 8) * NC + col) = make_float2(v2, v3);
        }
    }
}

// ---------------- gather place/src rows into cat, zero dst section ----------------
__global__ void k_gather(const int* __restrict__ place_idx, const int* __restrict__ src_idx,
                         const int* __restrict__ t_idx) {
    int idx = blockIdx.x * blockDim.x + threadIdx.x;
    if (idx >= PP * HH) return;
    int p = idx >> 7, f = idx & 127;
    int t = t_idx[p];
    size_t fb = (size_t)t * NN * HH;
    size_t cb = (size_t)p * CATW;
    g_cat[cb + f]          = g_feats[fb + (size_t)place_idx[p] * HH + f];
    g_cat[cb + HH + f]     = g_feats[fb + (size_t)src_idx[p] * HH + f];
    g_cat[cb + 2 * HH + f] = 0.f;
}

__global__ void k_scatter_dst(const int* __restrict__ dst_nodes, const int* __restrict__ dst_seg,
                              const int* __restrict__ t_idx) {
    int idx = blockIdx.x * blockDim.x + threadIdx.x;
    if (idx >= DD * HH) return;
    int d = idx >> 7, f = idx & 127;
    int row = dst_seg[d];
    int t = t_idx[row];
    float v = g_feats[((size_t)t * NN + dst_nodes[d]) * HH + f];
    atomicAdd(&g_cat[(size_t)row * CATW + 2 * HH + f], v);
}

// ---------------- logits + log_softmax (warp per row) ----------------
__global__ void k_logits(const float* __restrict__ Wd2, const float* __restrict__ bd2) {
    int warp = (blockIdx.x * blockDim.x + threadIdx.x) >> 5;
    int lane = threadIdx.x & 31;
    if (warp >= PP) return;
    const float* hrow = g_hidden + (size_t)warp * CATW;
    float a0 = 0.f, a1 = 0.f;
    for (int k = lane; k < CATW; k += 32) {
        float hv = hrow[k];
        a0 += hv * __ldg(&Wd2[k * 2]);
        a1 += hv * __ldg(&Wd2[k * 2 + 1]);
    }
#pragma unroll
    for (int o = 16; o; o >>= 1) {
        a0 += __shfl_down_sync(0xffffffffu, a0, o);
        a1 += __shfl_down_sync(0xffffffffu, a1, o);
    }
    if (lane == 0) {
        a0 += bd2[0];
        a1 += bd2[1];
        float m = fmaxf(a0, a1);
        float lse = m + logf(expf(a0 - m) + expf(a1 - m));
        g_logprob[warp * 2]     = a0 - lse;
        g_logprob[warp * 2 + 1] = a1 - lse;
    }
}

// ---------------- group / variant bookkeeping ----------------
__global__ void k_group_sum(const int* __restrict__ group_id) {
    int p = blockIdx.x * blockDim.x + threadIdx.x;
    if (p >= PP) return;
    int g = group_id[p];
    atomicAdd(&g_gsum[g * 2 + 0], (double)g_logprob[p * 2 + 0]);
    atomicAdd(&g_gsum[g * 2 + 1], (double)g_logprob[p * 2 + 1]);
}

__global__ void k_var_starts(const int* __restrict__ vg) {
    int g = blockIdx.x * blockDim.x + threadIdx.x;
    if (g >= GG) return;
    int v = vg[g];
    if (g == 0 || vg[g - 1] != v) g_vstart[v] = g;
}

__global__ void k_within(const int* __restrict__ vg) {
    int v = blockIdx.x * blockDim.x + threadIdx.x;
    if (v >= VV) return;
    int g = g_vstart[v];
    if (g < 0) return;
    double r0 = 0.0, r1 = 0.0;
    while (g < GG && vg[g] == v) {
        r0 += g_gsum[g * 2];
        r1 += g_gsum[g * 2 + 1];
        g_within[g * 2]     = (float)r0;
        g_within[g * 2 + 1] = (float)r1;
        g++;
    }
}

__global__ void k_logc(const float* __restrict__ counts) {
    __shared__ double red[8];
    double s = 0.0;
    for (int v = threadIdx.x; v < VV; v += blockDim.x) s += (double)counts[v];
#pragma unroll
    for (int o = 16; o; o >>= 1) s += __shfl_down_sync(0xffffffffu, s, o);
    if ((threadIdx.x & 31) == 0) red[threadIdx.x >> 5] = s;
    __syncthreads();
    double tot = 0.0;
#pragma unroll
    for (int i = 0; i < 8; i++) tot += red[i];
    for (int v = threadIdx.x; v < VV; v += blockDim.x)
        g_logc[v] = logf((float)((double)counts[v] / tot));
}

__global__ void k_finalize(const int* __restrict__ group_id, const int* __restrict__ vg,
                           const int* __restrict__ place_idx, float* __restrict__ out) {
    int idx = blockIdx.x * blockDim.x + threadIdx.x;
    if (idx >= PP * 2) return;
    int p = idx >> 1, o = idx & 1;
    int g = group_id[p];
    float add = g_logprob[idx] + g_within[g * 2 + o] + g_logc[vg[g]];
    atomicAdd(&out[place_idx[p] * 2 + o], add);
}

// ---------------- host launch ----------------
extern "C" void kernel_launch(void* const* d_in, const int* in_sizes, int n_in,
                              void* d_out, int out_size) {
    const float* x      = (const float*)d_in[0];
    const float* Wes    = (const float*)d_in[1];
    const float* Wen    = (const float*)d_in[2];
    const float* benc   = (const float*)d_in[3];
    const float* W2s    = (const float*)d_in[4];
    const float* W2n    = (const float*)d_in[5];
    const float* b2     = (const float*)d_in[6];
    const float* Wd1    = (const float*)d_in[7];
    const float* bd1    = (const float*)d_in[8];
    const float* Wd2    = (const float*)d_in[9];
    const float* bd2    = (const float*)d_in[10];
    const float* counts = (const float*)d_in[11];
    const int* edge_src = (const int*)d_in[12];
    const int* edge_dst = (const int*)d_in[13];
    const int* place_idx = (const int*)d_in[14];
    const int* src_idx   = (const int*)d_in[15];
    const int* t_idx     = (const int*)d_in[16];
    const int* dst_nodes = (const int*)d_in[17];
    const int* dst_seg   = (const int*)d_in[18];
    const int* group_id  = (const int*)d_in[19];
    const int* vg        = (const int*)d_in[20];
    float* out = (float*)d_out;

    void *p_deg, *p_gsum, *p_vstart, *p_feats, *p_agg, *p_cat, *p_hidden;
    cudaGetSymbolAddress(&p_deg, g_deg);
    cudaGetSymbolAddress(&p_gsum, g_gsum);
    cudaGetSymbolAddress(&p_vstart, g_vstart);
    cudaGetSymbolAddress(&p_feats, g_feats);
    cudaGetSymbolAddress(&p_agg, g_agg);
    cudaGetSymbolAddress(&p_cat, g_cat);
    cudaGetSymbolAddress(&p_hidden, g_hidden);
    float* feats = (float*)p_feats;
    float* agg   = (float*)p_agg;
    float* cat   = (float*)p_cat;
    float* hid   = (float*)p_hidden;

    // --- CSR build ---
    cudaMemsetAsync(p_deg, 0, NN * sizeof(int));
    k_count_deg<<<(EE + 255) / 256, 256>>>(edge_dst);
    k_scan<<<1, 1024>>>();
    k_fill<<<(EE + 255) / 256, 256>>>(edge_src, edge_dst);

    dim3 gemmGridN(1, (NN + 127) / 128);

    // --- encoder: h0 = relu(x@Wes + agg(x)@Wen + b) ---
    k_aggregate<FINF><<<(NN + 3) / 4, dim3(FINF, 4)>>>(x);
    k_gemm_tc<<<gemmGridN, 256>>>(x, FINF, agg, FINF, Wes, Wen, benc,
                                  feats, NN, HH, 1);

    // --- T recurrent steps ---
    for (int t = 1; t <= TT; t++) {
        const float* hp = feats + (size_t)(t - 1) * NN * HH;
        float* hn = feats + (size_t)t * NN * HH;
        k_aggregate<HH><<<(NN + 1) / 2, dim3(HH, 2)>>>(hp);
        k_gemm_tc<<<gemmGridN, 256>>>(hp, HH, agg, HH, W2s, W2n, b2,
                                      hn, NN, HH, 1);
    }

    // --- build cat = [place_f | src_f | dst_f] ---
    k_gather<<<(PP * HH + 255) / 256, 256>>>(place_idx, src_idx, t_idx);
    k_scatter_dst<<<(DD * HH + 255) / 256, 256>>>(dst_nodes, dst_seg, t_idx);

    // --- decoder hidden = relu(cat@Wd1 + bd1) ---
    dim3 gemmGridP(CATW / 128, (PP + 127) / 128);
    k_gemm_tc<<<gemmGridP, 256>>>(cat, CATW, nullptr, 0, Wd1, nullptr, bd1,
                                  hid, PP, CATW, 1);

    // --- logits + log_softmax ---
    k_logits<<<(PP + 7) / 8, 256>>>(Wd2, bd2);

    // --- group / variant running sums ---
    cudaMemsetAsync(p_gsum, 0, GG * 2 * sizeof(double));
    cudaMemsetAsync(p_vstart, 0xFF, VV * sizeof(int));
    k_group_sum<<<(PP + 255) / 256, 256>>>(group_id);
    k_var_starts<<<(GG + 255) / 256, 256>>>(vg);
    k_logc<<<1, 256>>>(counts);
    k_within<<<(VV + 255) / 256, 256>>>(vg);

    // --- output scatter ---
    cudaMemsetAsync(d_out, 0, (size_t)out_size * sizeof(float));
    k_finalize<<<(PP * 2 + 255) / 256, 256>>>(group_id, vg, place_idx, out);
}

// round 3
// speedup vs baseline: 1.4371x; 1.4371x over previous
#include <cuda_runtime.h>
#include <math.h>
#include <stdint.h>

#define NN  50000
#define FINF 64
#define HH  128
#define EE  800000
#define TT  8
#define PP  250000
#define DD  500000
#define GG  20000
#define VV  2000
#define CATW 384

// ---------------- scratch (device globals; no allocation allowed) ----------------
__device__ __align__(16) float  g_feats[(size_t)(TT + 1) * NN * HH];
__device__ __align__(16) float  g_agg[(size_t)NN * HH];
__device__ __align__(16) float  g_cat[(size_t)PP * CATW];
__device__ __align__(16) float  g_hidden[(size_t)PP * CATW];
__device__ float  g_logprob[PP * 2];
__device__ double g_gsum[GG * 2];
__device__ float  g_within[GG * 2];
__device__ int    g_deg[NN];
__device__ float  g_invdeg[NN];
__device__ int    g_rowptr[NN + 1];
__device__ int    g_cursor[NN];
__device__ int    g_csr[EE];
__device__ int    g_vstart[VV];
__device__ float  g_logc[VV];
__device__ int    g_dstart[PP + 1];

// ---------------- packed fp32x2 helpers ----------------
__device__ __forceinline__ unsigned long long pk2(float lo, float hi) {
    unsigned long long r;
    asm("mov.b64 %0, {%1, %2};" : "=l"(r) : "f"(lo), "f"(hi));
    return r;
}
__device__ __forceinline__ void upk2(unsigned long long v, float& lo, float& hi) {
    asm("mov.b64 {%0, %1}, %2;" : "=f"(lo), "=f"(hi) : "l"(v));
}
#define FFMA2(c, a, b) \
    asm("fma.rn.f32x2 %0, %1, %2, %3;" : "=l"(c) : "l"(a), "l"(b), "l"(c))

// ---------------- CSR build ----------------
__global__ void k_count_deg(const int* __restrict__ edge_dst) {
    int e = blockIdx.x * blockDim.x + threadIdx.x;
    if (e < EE) atomicAdd(&g_deg[edge_dst[e]], 1);
}

__global__ void k_scan() {
    __shared__ int warpsum[32];
    __shared__ int s_carry;
    if (threadIdx.x == 0) s_carry = 0;
    __syncthreads();
    int lane = threadIdx.x & 31, w = threadIdx.x >> 5;
    for (int base = 0; base < NN; base += 1024) {
        int i = base + threadIdx.x;
        int v = (i < NN) ? g_deg[i] : 0;
        int s = v;
#pragma unroll
        for (int o = 1; o < 32; o <<= 1) {
            int t = __shfl_up_sync(0xffffffffu, s, o);
            if (lane >= o) s += t;
        }
        if (lane == 31) warpsum[w] = s;
        __syncthreads();
        if (w == 0) {
            int ws = warpsum[lane];
#pragma unroll
            for (int o = 1; o < 32; o <<= 1) {
                int t = __shfl_up_sync(0xffffffffu, ws, o);
                if (lane >= o) ws += t;
            }
            warpsum[lane] = ws;
        }
        __syncthreads();
        int incl = s + (w > 0 ? warpsum[w - 1] : 0) + s_carry;
        if (i < NN) {
            g_rowptr[i + 1] = incl;
            g_cursor[i] = incl - v;
            g_invdeg[i] = 1.0f / (float)(v > 1 ? v : 1);
            if (i == 0) g_rowptr[0] = 0;
        }
        __syncthreads();
        if (threadIdx.x == 1023) s_carry = incl;
        __syncthreads();
    }
}

__global__ void k_fill(const int* __restrict__ edge_src, const int* __restrict__ edge_dst) {
    int e = blockIdx.x * blockDim.x + threadIdx.x;
    if (e >= EE) return;
    int pos = atomicAdd(&g_cursor[edge_dst[e]], 1);
    g_csr[pos] = edge_src[e];
}

// ---------------- mean aggregation (atomic-free via CSR, float4) ----------------
template <int F>
__global__ void k_aggregate4(const float* __restrict__ h) {
    int node = blockIdx.x * blockDim.y + threadIdx.y;
    if (node >= NN) return;
    int f4 = threadIdx.x;  // [0, F/4)
    int e0 = g_rowptr[node], e1 = g_rowptr[node + 1];
    float4 s = make_float4(0.f, 0.f, 0.f, 0.f);
    for (int e = e0; e < e1; e++) {
        int src = g_csr[e];
        float4 v = *(const float4*)(h + (size_t)src * F + f4 * 4);
        s.x += v.x; s.y += v.y; s.z += v.z; s.w += v.w;
    }
    float id = g_invdeg[node];
    s.x *= id; s.y *= id; s.z *= id; s.w *= id;
    *(float4*)(g_agg + (size_t)node * F + f4 * 4) = s;
}

// ---------------- fp32 SIMT GEMM with FFMA2 + ping-pong smem ----------------
// C = act(A1@W1 [+ A2@W2] + bias), BM=BN=128, BK=8, 256 threads, 8x8/thread.
#define BSTR 132  // padded row stride in words

__global__ __launch_bounds__(256) void k_sgemm_dual(
    const float* __restrict__ A1, int K1,
    const float* __restrict__ A2, int K2,
    const float* __restrict__ W1, const float* __restrict__ W2,
    const float* __restrict__ bias,
    float* __restrict__ C, int M, int NC, int doRelu)
{
    __shared__ __align__(16) float As[2][8][BSTR];
    __shared__ __align__(16) float Bs[2][8][BSTR];
    int tid = threadIdx.x;
    int rowBlock = blockIdx.y * 128;
    int colBlock = blockIdx.x * 128;
    int tx = tid & 15, ty = tid >> 4;
    int rowBase = ty * 8, colBase = tx * 8;

    int la_m = tid >> 1;       // 0..127
    int la_k = (tid & 1) * 4;  // 0 / 4
    int lb_k = tid >> 5;       // 0..7
    int lb_n = (tid & 31) * 4; // 0..124

    unsigned long long acc2[8][4];
#pragma unroll
    for (int i = 0; i < 8; i++)
#pragma unroll
        for (int j = 0; j < 4; j++) acc2[i][j] = 0ull;

    int nt1 = K1 >> 3;
    int nt2 = (A2 != nullptr) ? (K2 >> 3) : 0;
    int nt = nt1 + nt2;

    float4 av, bv;
    {
        const float* A = A1; const float* W = W1; int K = K1; int k0 = 0;
        int gm = rowBlock + la_m;
        av = (gm < M) ? *(const float4*)(A + (size_t)gm * K + k0 + la_k)
                      : make_float4(0.f, 0.f, 0.f, 0.f);
        bv = *(const float4*)(W + (size_t)(k0 + lb_k) * NC + colBlock + lb_n);
    }
    // store tile 0 into buffer 0
    As[0][la_k + 0][la_m] = av.x;
    As[0][la_k + 1][la_m] = av.y;
    As[0][la_k + 2][la_m] = av.z;
    As[0][la_k + 3][la_m] = av.w;
    *(float4*)&Bs[0][lb_k][lb_n] = bv;
    __syncthreads();

    int s = 0;
#pragma unroll 1
    for (int t = 0; t < nt; t++) {
        // prefetch next tile to registers
        if (t + 1 < nt) {
            int tn = t + 1;
            const float* A; const float* W; int K; int k0;
            if (tn < nt1) { A = A1; W = W1; K = K1; k0 = tn * 8; }
            else          { A = A2; W = W2; K = K2; k0 = (tn - nt1) * 8; }
            int gm = rowBlock + la_m;
            av = (gm < M) ? *(const float4*)(A + (size_t)gm * K + k0 + la_k)
                          : make_float4(0.f, 0.f, 0.f, 0.f);
            bv = *(const float4*)(W + (size_t)(k0 + lb_k) * NC + colBlock + lb_n);
        }
        // compute from buffer s
#pragma unroll
        for (int k = 0; k < 8; k++) {
            float4 a0 = *(const float4*)&As[s][k][rowBase];
            float4 a1 = *(const float4*)&As[s][k][rowBase + 4];
            float4 b0 = *(const float4*)&Bs[s][k][colBase];
            float4 b1 = *(const float4*)&Bs[s][k][colBase + 4];
            unsigned long long rbp[4];
            rbp[0] = pk2(b0.x, b0.y);
            rbp[1] = pk2(b0.z, b0.w);
            rbp[2] = pk2(b1.x, b1.y);
            rbp[3] = pk2(b1.z, b1.w);
            float ra[8] = {a0.x, a0.y, a0.z, a0.w, a1.x, a1.y, a1.z, a1.w};
#pragma unroll
            for (int i = 0; i < 8; i++) {
                unsigned long long rai = pk2(ra[i], ra[i]);
#pragma unroll
                for (int j = 0; j < 4; j++) FFMA2(acc2[i][j], rai, rbp[j]);
            }
        }
        // store prefetched tile into the other buffer
        if (t + 1 < nt) {
            int sn = s ^ 1;
            As[sn][la_k + 0][la_m] = av.x;
            As[sn][la_k + 1][la_m] = av.y;
            As[sn][la_k + 2][la_m] = av.z;
            As[sn][la_k + 3][la_m] = av.w;
            *(float4*)&Bs[sn][lb_k][lb_n] = bv;
        }
        __syncthreads();
        s ^= 1;
    }

    // epilogue: bias + optional relu
    float4 bb0 = *(const float4*)(bias + colBlock + colBase);
    float4 bb1 = *(const float4*)(bias + colBlock + colBase + 4);
    float bbs[8] = {bb0.x, bb0.y, bb0.z, bb0.w, bb1.x, bb1.y, bb1.z, bb1.w};
#pragma unroll
    for (int i = 0; i < 8; i++) {
        int gm = rowBlock + rowBase + i;
        if (gm >= M) continue;
        float o[8];
#pragma unroll
        for (int j = 0; j < 4; j++) upk2(acc2[i][j], o[j * 2], o[j * 2 + 1]);
#pragma unroll
        for (int j = 0; j < 8; j++) {
            o[j] += bbs[j];
            if (doRelu) o[j] = fmaxf(o[j], 0.f);
        }
        float* cp = C + (size_t)gm * NC + colBlock + colBase;
        *(float4*)cp       = make_float4(o[0], o[1], o[2], o[3]);
        *(float4*)(cp + 4) = make_float4(o[4], o[5], o[6], o[7]);
    }
}

// ---------------- gather place/src rows into cat (float4) ----------------
__global__ void k_gather(const int* __restrict__ place_idx, const int* __restrict__ src_idx,
                         const int* __restrict__ t_idx) {
    int idx = blockIdx.x * blockDim.x + threadIdx.x;
    if (idx >= PP * 32) return;
    int p = idx >> 5, q = idx & 31;
    int t = t_idx[p];
    size_t fb = (size_t)t * NN * HH;
    size_t cb = (size_t)p * CATW + q * 4;
    *(float4*)(g_cat + cb)      = *(const float4*)(g_feats + fb + (size_t)place_idx[p] * HH + q * 4);
    *(float4*)(g_cat + cb + HH) = *(const float4*)(g_feats + fb + (size_t)src_idx[p] * HH + q * 4);
}

// ---------------- dst segment-sum (atomic-free; dst_seg is sorted) ----------------
__global__ void k_dst_bounds(const int* __restrict__ dst_seg) {
    int p = blockIdx.x * blockDim.x + threadIdx.x;
    if (p > PP) return;
    int lo = 0, hi = DD;
    while (lo < hi) {
        int mid = (lo + hi) >> 1;
        if (dst_seg[mid] < p) lo = mid + 1; else hi = mid;
    }
    g_dstart[p] = lo;
}

__global__ void k_dst_sum(const int* __restrict__ dst_nodes, const int* __restrict__ t_idx) {
    int idx = blockIdx.x * blockDim.x + threadIdx.x;
    if (idx >= PP * 32) return;
    int p = idx >> 5, q = idx & 31;
    int e0 = g_dstart[p], e1 = g_dstart[p + 1];
    const float* base = g_feats + (size_t)t_idx[p] * NN * HH + q * 4;
    float4 s = make_float4(0.f, 0.f, 0.f, 0.f);
    for (int e = e0; e < e1; e++) {
        float4 v = *(const float4*)(base + (size_t)dst_nodes[e] * HH);
        s.x += v.x; s.y += v.y; s.z += v.z; s.w += v.w;
    }
    *(float4*)(g_cat + (size_t)p * CATW + 2 * HH + q * 4) = s;
}

// ---------------- logits + log_softmax (warp per row) ----------------
__global__ void k_logits(const float* __restrict__ Wd2, const float* __restrict__ bd2) {
    int warp = (blockIdx.x * blockDim.x + threadIdx.x) >> 5;
    int lane = threadIdx.x & 31;
    if (warp >= PP) return;
    const float* hrow = g_hidden + (size_t)warp * CATW;
    float a0 = 0.f, a1 = 0.f;
#pragma unroll
    for (int kb = 0; kb < 3; kb++) {
        int k = kb * 128 + lane * 4;
        float4 hv = *(const float4*)(hrow + k);
        float4 w0 = *(const float4*)(Wd2 + k * 2);
        float4 w1 = *(const float4*)(Wd2 + k * 2 + 4);
        a0 += hv.x * w0.x + hv.y * w0.z + hv.z * w1.x + hv.w * w1.z;
        a1 += hv.x * w0.y + hv.y * w0.w + hv.z * w1.y + hv.w * w1.w;
    }
#pragma unroll
    for (int o = 16; o; o >>= 1) {
        a0 += __shfl_down_sync(0xffffffffu, a0, o);
        a1 += __shfl_down_sync(0xffffffffu, a1, o);
    }
    if (lane == 0) {
        a0 += bd2[0];
        a1 += bd2[1];
        float m = fmaxf(a0, a1);
        float lse = m + logf(expf(a0 - m) + expf(a1 - m));
        g_logprob[warp * 2]     = a0 - lse;
        g_logprob[warp * 2 + 1] = a1 - lse;
    }
}

// ---------------- group / variant bookkeeping ----------------
__global__ void k_group_sum(const int* __restrict__ group_id) {
    int p = blockIdx.x * blockDim.x + threadIdx.x;
    if (p >= PP) return;
    int g = group_id[p];
    atomicAdd(&g_gsum[g * 2 + 0], (double)g_logprob[p * 2 + 0]);
    atomicAdd(&g_gsum[g * 2 + 1], (double)g_logprob[p * 2 + 1]);
}

__global__ void k_var_starts(const int* __restrict__ vg) {
    int g = blockIdx.x * blockDim.x + threadIdx.x;
    if (g >= GG) return;
    int v = vg[g];
    if (g == 0 || vg[g - 1] != v) g_vstart[v] = g;
}

__global__ void k_within(const int* __restrict__ vg) {
    int v = blockIdx.x * blockDim.x + threadIdx.x;
    if (v >= VV) return;
    int g = g_vstart[v];
    if (g < 0) return;
    double r0 = 0.0, r1 = 0.0;
    while (g < GG && vg[g] == v) {
        r0 += g_gsum[g * 2];
        r1 += g_gsum[g * 2 + 1];
        g_within[g * 2]     = (float)r0;
        g_within[g * 2 + 1] = (float)r1;
        g++;
    }
}

__global__ void k_logc(const float* __restrict__ counts) {
    __shared__ double red[8];
    double s = 0.0;
    for (int v = threadIdx.x; v < VV; v += blockDim.x) s += (double)counts[v];
#pragma unroll
    for (int o = 16; o; o >>= 1) s += __shfl_down_sync(0xffffffffu, s, o);
    if ((threadIdx.x & 31) == 0) red[threadIdx.x >> 5] = s;
    __syncthreads();
    double tot = 0.0;
#pragma unroll
    for (int i = 0; i < 8; i++) tot += red[i];
    for (int v = threadIdx.x; v < VV; v += blockDim.x)
        g_logc[v] = logf((float)((double)counts[v] / tot));
}

__global__ void k_finalize(const int* __restrict__ group_id, const int* __restrict__ vg,
                           const int* __restrict__ place_idx, float* __restrict__ out) {
    int idx = blockIdx.x * blockDim.x + threadIdx.x;
    if (idx >= PP * 2) return;
    int p = idx >> 1, o = idx & 1;
    int g = group_id[p];
    float add = g_logprob[idx] + g_within[g * 2 + o] + g_logc[vg[g]];
    atomicAdd(&out[place_idx[p] * 2 + o], add);
}

// ---------------- host launch ----------------
extern "C" void kernel_launch(void* const* d_in, const int* in_sizes, int n_in,
                              void* d_out, int out_size) {
    const float* x      = (const float*)d_in[0];
    const float* Wes    = (const float*)d_in[1];
    const float* Wen    = (const float*)d_in[2];
    const float* benc   = (const float*)d_in[3];
    const float* W2s    = (const float*)d_in[4];
    const float* W2n    = (const float*)d_in[5];
    const float* b2     = (const float*)d_in[6];
    const float* Wd1    = (const float*)d_in[7];
    const float* bd1    = (const float*)d_in[8];
    const float* Wd2    = (const float*)d_in[9];
    const float* bd2    = (const float*)d_in[10];
    const float* counts = (const float*)d_in[11];
    const int* edge_src = (const int*)d_in[12];
    const int* edge_dst = (const int*)d_in[13];
    const int* place_idx = (const int*)d_in[14];
    const int* src_idx   = (const int*)d_in[15];
    const int* t_idx     = (const int*)d_in[16];
    const int* dst_nodes = (const int*)d_in[17];
    const int* dst_seg   = (const int*)d_in[18];
    const int* group_id  = (const int*)d_in[19];
    const int* vg        = (const int*)d_in[20];
    float* out = (float*)d_out;

    void *p_deg, *p_gsum, *p_vstart, *p_feats, *p_agg, *p_cat, *p_hidden;
    cudaGetSymbolAddress(&p_deg, g_deg);
    cudaGetSymbolAddress(&p_gsum, g_gsum);
    cudaGetSymbolAddress(&p_vstart, g_vstart);
    cudaGetSymbolAddress(&p_feats, g_feats);
    cudaGetSymbolAddress(&p_agg, g_agg);
    cudaGetSymbolAddress(&p_cat, g_cat);
    cudaGetSymbolAddress(&p_hidden, g_hidden);
    float* feats = (float*)p_feats;
    float* agg   = (float*)p_agg;
    float* cat   = (float*)p_cat;
    float* hid   = (float*)p_hidden;

    // --- CSR build ---
    cudaMemsetAsync(p_deg, 0, NN * sizeof(int));
    k_count_deg<<<(EE + 255) / 256, 256>>>(edge_dst);
    k_scan<<<1, 1024>>>();
    k_fill<<<(EE + 255) / 256, 256>>>(edge_src, edge_dst);

    dim3 gemmGridN(1, (NN + 127) / 128);

    // --- encoder: h0 = relu(x@Wes + agg(x)@Wen + b) ---
    k_aggregate4<FINF><<<(NN + 15) / 16, dim3(16, 16)>>>(x);
    k_sgemm_dual<<<gemmGridN, 256>>>(x, FINF, agg, FINF, Wes, Wen, benc,
                                     feats, NN, HH, 1);

    // --- T recurrent steps ---
    for (int t = 1; t <= TT; t++) {
        const float* hp = feats + (size_t)(t - 1) * NN * HH;
        float* hn = feats + (size_t)t * NN * HH;
        k_aggregate4<HH><<<(NN + 7) / 8, dim3(32, 8)>>>(hp);
        k_sgemm_dual<<<gemmGridN, 256>>>(hp, HH, agg, HH, W2s, W2n, b2,
                                         hn, NN, HH, 1);
    }

    // --- build cat = [place_f | src_f | dst_f] ---
    k_gather<<<(PP * 32 + 255) / 256, 256>>>(place_idx, src_idx, t_idx);
    k_dst_bounds<<<(PP + 256) / 256, 256>>>(dst_seg);
    k_dst_sum<<<(PP * 32 + 255) / 256, 256>>>(dst_nodes, t_idx);

    // --- decoder hidden = relu(cat@Wd1 + bd1) ---
    dim3 gemmGridP(CATW / 128, (PP + 127) / 128);
    k_sgemm_dual<<<gemmGridP, 256>>>(cat, CATW, nullptr, 0, Wd1, nullptr, bd1,
                                     hid, PP, CATW, 1);

    // --- logits + log_softmax ---
    k_logits<<<(PP + 7) / 8, 256>>>(Wd2, bd2);

    // --- group / variant running sums ---
    cudaMemsetAsync(p_gsum, 0, GG * 2 * sizeof(double));
    cudaMemsetAsync(p_vstart, 0xFF, VV * sizeof(int));
    k_group_sum<<<(PP + 255) / 256, 256>>>(group_id);
    k_var_starts<<<(GG + 255) / 256, 256>>>(vg);
    k_logc<<<1, 256>>>(counts);
    k_within<<<(VV + 255) / 256, 256>>>(vg);

    // --- output scatter ---
    cudaMemsetAsync(d_out, 0, (size_t)out_size * sizeof(float));
    k_finalize<<<(PP * 2 + 255) / 256, 256>>>(group_id, vg, place_idx, out);
}

// round 7
// speedup vs baseline: 1.5210x; 1.0584x over previous
#include <cuda_runtime.h>
#include <math.h>
#include <stdint.h>

#define NN  50000
#define FINF 64
#define HH  128
#define EE  800000
#define TT  8
#define PP  250000
#define DD  500000
#define GG  20000
#define VV  2000
#define CATW 384

// ---------------- scratch (device globals; no allocation allowed) ----------------
__device__ __align__(16) float  g_feats[(size_t)(TT + 1) * NN * HH];
__device__ __align__(16) float  g_agg[(size_t)NN * HH];
__device__ __align__(16) float  g_dstf[(size_t)PP * HH];     // dst segment sums [P,128]
__device__ float  g_logit[PP * 2];
__device__ float  g_logprob[PP * 2];
__device__ double g_gsum[GG * 2];
__device__ float  g_within[GG * 2];
__device__ int    g_deg[NN];
__device__ float  g_invdeg[NN];
__device__ int    g_rowptr[NN + 1];
__device__ int    g_cursor[NN];
__device__ int    g_csr[EE];
__device__ int    g_vstart[VV];
__device__ float  g_logc[VV];
__device__ int    g_dstart[PP + 1];

// ---------------- packed fp32x2 helpers ----------------
__device__ __forceinline__ unsigned long long pk2(float lo, float hi) {
    unsigned long long r;
    asm("mov.b64 %0, {%1, %2};" : "=l"(r) : "f"(lo), "f"(hi));
    return r;
}
__device__ __forceinline__ void upk2(unsigned long long v, float& lo, float& hi) {
    asm("mov.b64 {%0, %1}, %2;" : "=f"(lo), "=f"(hi) : "l"(v));
}
#define FFMA2(c, a, b) \
    asm("fma.rn.f32x2 %0, %1, %2, %3;" : "=l"(c) : "l"(a), "l"(b), "l"(c))

// ---------------- CSR build ----------------
__global__ void k_count_deg(const int* __restrict__ edge_dst) {
    int e = blockIdx.x * blockDim.x + threadIdx.x;
    if (e < EE) atomicAdd(&g_deg[edge_dst[e]], 1);
}

__global__ void k_scan() {
    __shared__ int warpsum[32];
    __shared__ int s_carry;
    if (threadIdx.x == 0) s_carry = 0;
    __syncthreads();
    int lane = threadIdx.x & 31, w = threadIdx.x >> 5;
    for (int base = 0; base < NN; base += 1024) {
        int i = base + threadIdx.x;
        int v = (i < NN) ? g_deg[i] : 0;
        int s = v;
#pragma unroll
        for (int o = 1; o < 32; o <<= 1) {
            int t = __shfl_up_sync(0xffffffffu, s, o);
            if (lane >= o) s += t;
        }
        if (lane == 31) warpsum[w] = s;
        __syncthreads();
        if (w == 0) {
            int ws = warpsum[lane];
#pragma unroll
            for (int o = 1; o < 32; o <<= 1) {
                int t = __shfl_up_sync(0xffffffffu, ws, o);
                if (lane >= o) ws += t;
            }
            warpsum[lane] = ws;
        }
        __syncthreads();
        int incl = s + (w > 0 ? warpsum[w - 1] : 0) + s_carry;
        if (i < NN) {
            g_rowptr[i + 1] = incl;
            g_cursor[i] = incl - v;
            g_invdeg[i] = 1.0f / (float)(v > 1 ? v : 1);
            if (i == 0) g_rowptr[0] = 0;
        }
        __syncthreads();
        if (threadIdx.x == 1023) s_carry = incl;
        __syncthreads();
    }
}

__global__ void k_fill(const int* __restrict__ edge_src, const int* __restrict__ edge_dst) {
    int e = blockIdx.x * blockDim.x + threadIdx.x;
    if (e >= EE) return;
    int pos = atomicAdd(&g_cursor[edge_dst[e]], 1);
    g_csr[pos] = edge_src[e];
}

// ---------------- mean aggregation (atomic-free via CSR, float4) ----------------
template <int F>
__global__ void k_aggregate4(const float* __restrict__ h) {
    int node = blockIdx.x * blockDim.y + threadIdx.y;
    if (node >= NN) return;
    int f4 = threadIdx.x;
    int e0 = g_rowptr[node], e1 = g_rowptr[node + 1];
    float4 s = make_float4(0.f, 0.f, 0.f, 0.f);
    for (int e = e0; e < e1; e++) {
        int src = g_csr[e];
        float4 v = *(const float4*)(h + (size_t)src * F + f4 * 4);
        s.x += v.x; s.y += v.y; s.z += v.z; s.w += v.w;
    }
    float id = g_invdeg[node];
    s.x *= id; s.y *= id; s.z *= id; s.w *= id;
    *(float4*)(g_agg + (size_t)node * F + f4 * 4) = s;
}

// ---------------- MP GEMM: C = relu(A1@W1 + A2@W2 + bias), FFMA2 + ping-pong ----
#define BSTR 132

__global__ __launch_bounds__(256) void k_sgemm_dual(
    const float* __restrict__ A1, int K1,
    const float* __restrict__ A2, int K2,
    const float* __restrict__ W1, const float* __restrict__ W2,
    const float* __restrict__ bias,
    float* __restrict__ C, int M, int NC)
{
    __shared__ __align__(16) float As[2][8][BSTR];
    __shared__ __align__(16) float Bs[2][8][BSTR];
    int tid = threadIdx.x;
    int rowBlock = blockIdx.y * 128;
    int colBlock = blockIdx.x * 128;
    int tx = tid & 15, ty = tid >> 4;
    int rowBase = ty * 8, colBase = tx * 8;

    int la_m = tid >> 1;
    int la_k = (tid & 1) * 4;
    int lb_k = tid >> 5;
    int lb_n = (tid & 31) * 4;

    unsigned long long acc2[8][4];
#pragma unroll
    for (int i = 0; i < 8; i++)
#pragma unroll
        for (int j = 0; j < 4; j++) acc2[i][j] = 0ull;

    int nt1 = K1 >> 3;
    int nt = nt1 + (K2 >> 3);

    float4 av, bv;
    {
        int gm = rowBlock + la_m;
        av = (gm < M) ? *(const float4*)(A1 + (size_t)gm * K1 + la_k)
                      : make_float4(0.f, 0.f, 0.f, 0.f);
        bv = *(const float4*)(W1 + (size_t)lb_k * NC + colBlock + lb_n);
    }
    As[0][la_k + 0][la_m] = av.x;
    As[0][la_k + 1][la_m] = av.y;
    As[0][la_k + 2][la_m] = av.z;
    As[0][la_k + 3][la_m] = av.w;
    *(float4*)&Bs[0][lb_k][lb_n] = bv;
    __syncthreads();

    int s = 0;
#pragma unroll 1
    for (int t = 0; t < nt; t++) {
        if (t + 1 < nt) {
            int tn = t + 1;
            const float* A; const float* W; int K; int k0;
            if (tn < nt1) { A = A1; W = W1; K = K1; k0 = tn * 8; }
            else          { A = A2; W = W2; K = K2; k0 = (tn - nt1) * 8; }
            int gm = rowBlock + la_m;
            av = (gm < M) ? *(const float4*)(A + (size_t)gm * K + k0 + la_k)
                          : make_float4(0.f, 0.f, 0.f, 0.f);
            bv = *(const float4*)(W + (size_t)(k0 + lb_k) * NC + colBlock + lb_n);
        }
#pragma unroll
        for (int k = 0; k < 8; k++) {
            float4 a0 = *(const float4*)&As[s][k][rowBase];
            float4 a1 = *(const float4*)&As[s][k][rowBase + 4];
            float4 b0 = *(const float4*)&Bs[s][k][colBase];
            float4 b1 = *(const float4*)&Bs[s][k][colBase + 4];
            unsigned long long rbp[4];
            rbp[0] = pk2(b0.x, b0.y);
            rbp[1] = pk2(b0.z, b0.w);
            rbp[2] = pk2(b1.x, b1.y);
            rbp[3] = pk2(b1.z, b1.w);
            float ra[8] = {a0.x, a0.y, a0.z, a0.w, a1.x, a1.y, a1.z, a1.w};
#pragma unroll
            for (int i = 0; i < 8; i++) {
                unsigned long long rai = pk2(ra[i], ra[i]);
#pragma unroll
                for (int j = 0; j < 4; j++) FFMA2(acc2[i][j], rai, rbp[j]);
            }
        }
        if (t + 1 < nt) {
            int sn = s ^ 1;
            As[sn][la_k + 0][la_m] = av.x;
            As[sn][la_k + 1][la_m] = av.y;
            As[sn][la_k + 2][la_m] = av.z;
            As[sn][la_k + 3][la_m] = av.w;
            *(float4*)&Bs[sn][lb_k][lb_n] = bv;
        }
        __syncthreads();
        s ^= 1;
    }

    float4 bb0 = *(const float4*)(bias + colBlock + colBase);
    float4 bb1 = *(const float4*)(bias + colBlock + colBase + 4);
    float bbs[8] = {bb0.x, bb0.y, bb0.z, bb0.w, bb1.x, bb1.y, bb1.z, bb1.w};
#pragma unroll
    for (int i = 0; i < 8; i++) {
        int gm = rowBlock + rowBase + i;
        if (gm >= M) continue;
        float o[8];
#pragma unroll
        for (int j = 0; j < 4; j++) upk2(acc2[i][j], o[j * 2], o[j * 2 + 1]);
#pragma unroll
        for (int j = 0; j < 8; j++) o[j] = fmaxf(o[j] + bbs[j], 0.f);
        float* cp = C + (size_t)gm * NC + colBlock + colBase;
        *(float4*)cp       = make_float4(o[0], o[1], o[2], o[3]);
        *(float4*)(cp + 4) = make_float4(o[4], o[5], o[6], o[7]);
    }
}

// ---------------- fused decoder: logit += relu(gathered_cat@Wd1 + bd1) @ Wd2 ----
// A rows gathered on the fly from feats (place / src) and g_dstf. No C store.
__global__ __launch_bounds__(256) void k_gemm_dec(
    const float* __restrict__ Wd1, const float* __restrict__ bd1,
    const float* __restrict__ Wd2,
    const int* __restrict__ place_idx, const int* __restrict__ src_idx,
    const int* __restrict__ t_idx)
{
    __shared__ __align__(16) float As[2][8][BSTR];
    __shared__ __align__(16) float Bs[2][8][BSTR];
    __shared__ __align__(16) float2 red[128][17];

    int tid = threadIdx.x;
    int rowBlock = blockIdx.y * 128;
    int colBlock = blockIdx.x * 128;
    int tx = tid & 15, ty = tid >> 4;
    int rowBase = ty * 8, colBase = tx * 8;

    int la_m = tid >> 1;
    int la_k = (tid & 1) * 4;
    int lb_k = tid >> 5;
    int lb_n = (tid & 31) * 4;

    // per-thread gather bases for the row this thread loads
    int gm = rowBlock + la_m;
    bool mok = gm < PP;
    const float* aptr[3] = {nullptr, nullptr, nullptr};
    if (mok) {
        int t = t_idx[gm];
        aptr[0] = g_feats + ((size_t)t * NN + place_idx[gm]) * HH;
        aptr[1] = g_feats + ((size_t)t * NN + src_idx[gm]) * HH;
        aptr[2] = g_dstf + (size_t)gm * HH;
    }

    unsigned long long acc2[8][4];
#pragma unroll
    for (int i = 0; i < 8; i++)
#pragma unroll
        for (int j = 0; j < 4; j++) acc2[i][j] = 0ull;

    const int nt = CATW / 8;  // 48

    float4 av, bv;
    av = mok ? *(const float4*)(aptr[0] + la_k) : make_float4(0.f, 0.f, 0.f, 0.f);
    bv = *(const float4*)(Wd1 + (size_t)lb_k * CATW + colBlock + lb_n);
    As[0][la_k + 0][la_m] = av.x;
    As[0][la_k + 1][la_m] = av.y;
    As[0][la_k + 2][la_m] = av.z;
    As[0][la_k + 3][la_m] = av.w;
    *(float4*)&Bs[0][lb_k][lb_n] = bv;
    __syncthreads();

    int s = 0;
#pragma unroll 1
    for (int t = 0; t < nt; t++) {
        if (t + 1 < nt) {
            int k0 = (t + 1) * 8;
            int seg = k0 >> 7, koff = k0 & 127;
            av = mok ? *(const float4*)(aptr[seg] + koff + la_k)
                     : make_float4(0.f, 0.f, 0.f, 0.f);
            bv = *(const float4*)(Wd1 + (size_t)(k0 + lb_k) * CATW + colBlock + lb_n);
        }
#pragma unroll
        for (int k = 0; k < 8; k++) {
            float4 a0 = *(const float4*)&As[s][k][rowBase];
            float4 a1 = *(const float4*)&As[s][k][rowBase + 4];
            float4 b0 = *(const float4*)&Bs[s][k][colBase];
            float4 b1 = *(const float4*)&Bs[s][k][colBase + 4];
            unsigned long long rbp[4];
            rbp[0] = pk2(b0.x, b0.y);
            rbp[1] = pk2(b0.z, b0.w);
            rbp[2] = pk2(b1.x, b1.y);
            rbp[3] = pk2(b1.z, b1.w);
            float ra[8] = {a0.x, a0.y, a0.z, a0.w, a1.x, a1.y, a1.z, a1.w};
#pragma unroll
            for (int i = 0; i < 8; i++) {
                unsigned long long rai = pk2(ra[i], ra[i]);
#pragma unroll
                for (int j = 0; j < 4; j++) FFMA2(acc2[i][j], rai, rbp[j]);
            }
        }
        if (t + 1 < nt) {
            int sn = s ^ 1;
            As[sn][la_k + 0][la_m] = av.x;
            As[sn][la_k + 1][la_m] = av.y;
            As[sn][la_k + 2][la_m] = av.z;
            As[sn][la_k + 3][la_m] = av.w;
            *(float4*)&Bs[sn][lb_k][lb_n] = bv;
        }
        __syncthreads();
        s ^= 1;
    }

    // epilogue: relu(acc + bd1) then project onto Wd2 columns, reduce, atomicAdd
    float4 bb0 = *(const float4*)(bd1 + colBlock + colBase);
    float4 bb1 = *(const float4*)(bd1 + colBlock + colBase + 4);
    float bbs[8] = {bb0.x, bb0.y, bb0.z, bb0.w, bb1.x, bb1.y, bb1.z, bb1.w};
    float w20[8], w21[8];
#pragma unroll
    for (int j = 0; j < 8; j++) {
        int col = colBlock + colBase + j;
        float2 w = *(const float2*)(Wd2 + col * 2);
        w20[j] = w.x; w21[j] = w.y;
    }
#pragma unroll
    for (int i = 0; i < 8; i++) {
        float o[8];
#pragma unroll
        for (int j = 0; j < 4; j++) upk2(acc2[i][j], o[j * 2], o[j * 2 + 1]);
        float pa0 = 0.f, pa1 = 0.f;
#pragma unroll
        for (int j = 0; j < 8; j++) {
            float h = fmaxf(o[j] + bbs[j], 0.f);
            pa0 += h * w20[j];
            pa1 += h * w21[j];
        }
        red[rowBase + i][tx] = make_float2(pa0, pa1);
    }
    __syncthreads();
    if (tid < 128) {
        int r = tid;
        float s0 = 0.f, s1 = 0.f;
#pragma unroll
        for (int c = 0; c < 16; c++) {
            float2 v = red[r][c];
            s0 += v.x; s1 += v.y;
        }
        int row = rowBlock + r;
        if (row < PP) {
            atomicAdd(&g_logit[row * 2], s0);
            atomicAdd(&g_logit[row * 2 + 1], s1);
        }
    }
}

// ---------------- dst segment-sum (atomic-free; dst_seg is sorted) ----------------
__global__ void k_dst_bounds(const int* __restrict__ dst_seg) {
    int p = blockIdx.x * blockDim.x + threadIdx.x;
    if (p > PP) return;
    int lo = 0, hi = DD;
    while (lo < hi) {
        int mid = (lo + hi) >> 1;
        if (dst_seg[mid] < p) lo = mid + 1; else hi = mid;
    }
    g_dstart[p] = lo;
}

__global__ void k_dst_sum(const int* __restrict__ dst_nodes, const int* __restrict__ t_idx) {
    int idx = blockIdx.x * blockDim.x + threadIdx.x;
    if (idx >= PP * 32) return;
    int p = idx >> 5, q = idx & 31;
    int e0 = g_dstart[p], e1 = g_dstart[p + 1];
    const float* base = g_feats + (size_t)t_idx[p] * NN * HH + q * 4;
    float4 s = make_float4(0.f, 0.f, 0.f, 0.f);
    for (int e = e0; e < e1; e++) {
        float4 v = *(const float4*)(base + (size_t)dst_nodes[e] * HH);
        s.x += v.x; s.y += v.y; s.z += v.z; s.w += v.w;
    }
    *(float4*)(g_dstf + (size_t)p * HH + q * 4) = s;
}

// ---------------- log_softmax over accumulated logits ----------------
__global__ void k_softmax(const float* __restrict__ bd2) {
    int p = blockIdx.x * blockDim.x + threadIdx.x;
    if (p >= PP) return;
    float a0 = g_logit[p * 2] + bd2[0];
    float a1 = g_logit[p * 2 + 1] + bd2[1];
    float m = fmaxf(a0, a1);
    float lse = m + logf(expf(a0 - m) + expf(a1 - m));
    g_logprob[p * 2]     = a0 - lse;
    g_logprob[p * 2 + 1] = a1 - lse;
}

// ---------------- group / variant bookkeeping ----------------
__global__ void k_group_sum(const int* __restrict__ group_id) {
    int p = blockIdx.x * blockDim.x + threadIdx.x;
    if (p >= PP) return;
    int g = group_id[p];
    atomicAdd(&g_gsum[g * 2 + 0], (double)g_logprob[p * 2 + 0]);
    atomicAdd(&g_gsum[g * 2 + 1], (double)g_logprob[p * 2 + 1]);
}

__global__ void k_var_starts(const int* __restrict__ vg) {
    int g = blockIdx.x * blockDim.x + threadIdx.x;
    if (g >= GG) return;
    int v = vg[g];
    if (g == 0 || vg[g - 1] != v) g_vstart[v] = g;
}

__global__ void k_within(const int* __restrict__ vg) {
    int v = blockIdx.x * blockDim.x + threadIdx.x;
    if (v >= VV) return;
    int g = g_vstart[v];
    if (g < 0) return;
    double r0 = 0.0, r1 = 0.0;
    while (g < GG && vg[g] == v) {
        r0 += g_gsum[g * 2];
        r1 += g_gsum[g * 2 + 1];
        g_within[g * 2]     = (float)r0;
        g_within[g * 2 + 1] = (float)r1;
        g++;
    }
}

__global__ void k_logc(const float* __restrict__ counts) {
    __shared__ double red[8];
    double s = 0.0;
    for (int v = threadIdx.x; v < VV; v += blockDim.x) s += (double)counts[v];
#pragma unroll
    for (int o = 16; o; o >>= 1) s += __shfl_down_sync(0xffffffffu, s, o);
    if ((threadIdx.x & 31) == 0) red[threadIdx.x >> 5] = s;
    __syncthreads();
    double tot = 0.0;
#pragma unroll
    for (int i = 0; i < 8; i++) tot += red[i];
    for (int v = threadIdx.x; v < VV; v += blockDim.x)
        g_logc[v] = logf((float)((double)counts[v] / tot));
}

__global__ void k_finalize(const int* __restrict__ group_id, const int* __restrict__ vg,
                           const int* __restrict__ place_idx, float* __restrict__ out) {
    int idx = blockIdx.x * blockDim.x + threadIdx.x;
    if (idx >= PP * 2) return;
    int p = idx >> 1, o = idx & 1;
    int g = group_id[p];
    float add = g_logprob[idx] + g_within[g * 2 + o] + g_logc[vg[g]];
    atomicAdd(&out[place_idx[p] * 2 + o], add);
}

// ---------------- host launch ----------------
extern "C" void kernel_launch(void* const* d_in, const int* in_sizes, int n_in,
                              void* d_out, int out_size) {
    const float* x      = (const float*)d_in[0];
    const float* Wes    = (const float*)d_in[1];
    const float* Wen    = (const float*)d_in[2];
    const float* benc   = (const float*)d_in[3];
    const float* W2s    = (const float*)d_in[4];
    const float* W2n    = (const float*)d_in[5];
    const float* b2     = (const float*)d_in[6];
    const float* Wd1    = (const float*)d_in[7];
    const float* bd1    = (const float*)d_in[8];
    const float* Wd2    = (const float*)d_in[9];
    const float* bd2    = (const float*)d_in[10];
    const float* counts = (const float*)d_in[11];
    const int* edge_src = (const int*)d_in[12];
    const int* edge_dst = (const int*)d_in[13];
    const int* place_idx = (const int*)d_in[14];
    const int* src_idx   = (const int*)d_in[15];
    const int* t_idx     = (const int*)d_in[16];
    const int* dst_nodes = (const int*)d_in[17];
    const int* dst_seg   = (const int*)d_in[18];
    const int* group_id  = (const int*)d_in[19];
    const int* vg        = (const int*)d_in[20];
    float* out = (float*)d_out;

    void *p_deg, *p_gsum, *p_vstart, *p_feats, *p_agg, *p_logit;
    cudaGetSymbolAddress(&p_deg, g_deg);
    cudaGetSymbolAddress(&p_gsum, g_gsum);
    cudaGetSymbolAddress(&p_vstart, g_vstart);
    cudaGetSymbolAddress(&p_feats, g_feats);
    cudaGetSymbolAddress(&p_agg, g_agg);
    cudaGetSymbolAddress(&p_logit, g_logit);
    float* feats = (float*)p_feats;
    float* agg   = (float*)p_agg;

    // --- CSR build ---
    cudaMemsetAsync(p_deg, 0, NN * sizeof(int));
    k_count_deg<<<(EE + 255) / 256, 256>>>(edge_dst);
    k_scan<<<1, 1024>>>();
    k_fill<<<(EE + 255) / 256, 256>>>(edge_src, edge_dst);

    dim3 gemmGridN(1, (NN + 127) / 128);

    // --- encoder ---
    k_aggregate4<FINF><<<(NN + 15) / 16, dim3(16, 16)>>>(x);
    k_sgemm_dual<<<gemmGridN, 256>>>(x, FINF, agg, FINF, Wes, Wen, benc,
                                     feats, NN, HH);

    // --- T recurrent steps ---
    for (int t = 1; t <= TT; t++) {
        const float* hp = feats + (size_t)(t - 1) * NN * HH;
        float* hn = feats + (size_t)t * NN * HH;
        k_aggregate4<HH><<<(NN + 7) / 8, dim3(32, 8)>>>(hp);
        k_sgemm_dual<<<gemmGridN, 256>>>(hp, HH, agg, HH, W2s, W2n, b2,
                                         hn, NN, HH);
    }

    // --- dst segment sums ---
    k_dst_bounds<<<(PP + 256) / 256, 256>>>(dst_seg);
    k_dst_sum<<<(PP * 32 + 255) / 256, 256>>>(dst_nodes, t_idx);

    // --- fused decoder GEMM + logit projection ---
    cudaMemsetAsync(p_logit, 0, PP * 2 * sizeof(float));
    dim3 gemmGridP(CATW / 128, (PP + 127) / 128);
    k_gemm_dec<<<gemmGridP, 256>>>(Wd1, bd1, Wd2, place_idx, src_idx, t_idx);

    // --- log_softmax ---
    k_softmax<<<(PP + 255) / 256, 256>>>(bd2);

    // --- group / variant running sums ---
    cudaMemsetAsync(p_gsum, 0, GG * 2 * sizeof(double));
    cudaMemsetAsync(p_vstart, 0xFF, VV * sizeof(int));
    k_group_sum<<<(PP + 255) / 256, 256>>>(group_id);
    k_var_starts<<<(GG + 255) / 256, 256>>>(vg);
    k_logc<<<1, 256>>>(counts);
    k_within<<<(VV + 255) / 256, 256>>>(vg);

    // --- output scatter ---
    cudaMemsetAsync(d_out, 0, (size_t)out_size * sizeof(float));
    k_finalize<<<(PP * 2 + 255) / 256, 256>>>(group_id, vg, place_idx, out);
}

// round 9
// speedup vs baseline: 1.5273x; 1.0041x over previous
#include <cuda_runtime.h>
#include <math.h>
#include <stdint.h>

#define NN  50000
#define FINF 64
#define HH  128
#define EE  800000
#define TT  8
#define PP  250000
#define DD  500000
#define GG  20000
#define VV  2000
#define CATW 384

// ---------------- scratch (device globals; no allocation allowed) ----------------
__device__ __align__(16) float  g_feats[(size_t)(TT + 1) * NN * HH];
__device__ __align__(16) float  g_agg[(size_t)NN * HH];
__device__ __align__(16) float  g_dstf[(size_t)PP * HH];
__device__ float  g_logprob[PP * 2];
__device__ double g_gsum[GG * 2];
__device__ float  g_within[GG * 2];
__device__ int    g_deg[NN];
__device__ float  g_invdeg[NN];
__device__ int    g_rowptr[NN + 1];
__device__ int    g_cursor[NN];
__device__ int    g_csr[EE];
__device__ int    g_vstart[VV];
__device__ float  g_logc[VV];
__device__ int    g_dstart[PP + 1];

// ---------------- packed fp32x2 helpers ----------------
__device__ __forceinline__ unsigned long long pk2(float lo, float hi) {
    unsigned long long r;
    asm("mov.b64 %0, {%1, %2};" : "=l"(r) : "f"(lo), "f"(hi));
    return r;
}
__device__ __forceinline__ void upk2(unsigned long long v, float& lo, float& hi) {
    asm("mov.b64 {%0, %1}, %2;" : "=f"(lo), "=f"(hi) : "l"(v));
}
#define FFMA2(c, a, b) \
    asm("fma.rn.f32x2 %0, %1, %2, %3;" : "=l"(c) : "l"(a), "l"(b), "l"(c))

// ---------------- CSR build ----------------
__global__ void k_count_deg(const int* __restrict__ edge_dst) {
    int e = blockIdx.x * blockDim.x + threadIdx.x;
    if (e < EE) atomicAdd(&g_deg[edge_dst[e]], 1);
}

__global__ void k_scan() {
    __shared__ int warpsum[32];
    __shared__ int s_carry;
    if (threadIdx.x == 0) s_carry = 0;
    __syncthreads();
    int lane = threadIdx.x & 31, w = threadIdx.x >> 5;
    for (int base = 0; base < NN; base += 1024) {
        int i = base + threadIdx.x;
        int v = (i < NN) ? g_deg[i] : 0;
        int s = v;
#pragma unroll
        for (int o = 1; o < 32; o <<= 1) {
            int t = __shfl_up_sync(0xffffffffu, s, o);
            if (lane >= o) s += t;
        }
        if (lane == 31) warpsum[w] = s;
        __syncthreads();
        if (w == 0) {
            int ws = warpsum[lane];
#pragma unroll
            for (int o = 1; o < 32; o <<= 1) {
                int t = __shfl_up_sync(0xffffffffu, ws, o);
                if (lane >= o) ws += t;
            }
            warpsum[lane] = ws;
        }
        __syncthreads();
        int incl = s + (w > 0 ? warpsum[w - 1] : 0) + s_carry;
        if (i < NN) {
            g_rowptr[i + 1] = incl;
            g_cursor[i] = incl - v;
            g_invdeg[i] = 1.0f / (float)(v > 1 ? v : 1);
            if (i == 0) g_rowptr[0] = 0;
        }
        __syncthreads();
        if (threadIdx.x == 1023) s_carry = incl;
        __syncthreads();
    }
}

__global__ void k_fill(const int* __restrict__ edge_src, const int* __restrict__ edge_dst) {
    int e = blockIdx.x * blockDim.x + threadIdx.x;
    if (e >= EE) return;
    int pos = atomicAdd(&g_cursor[edge_dst[e]], 1);
    g_csr[pos] = edge_src[e];
}

// ---------------- mean aggregation (atomic-free via CSR, float4) ----------------
template <int F>
__global__ void k_aggregate4(const float* __restrict__ h) {
    int node = blockIdx.x * blockDim.y + threadIdx.y;
    if (node >= NN) return;
    int f4 = threadIdx.x;
    int e0 = g_rowptr[node], e1 = g_rowptr[node + 1];
    float4 s = make_float4(0.f, 0.f, 0.f, 0.f);
    for (int e = e0; e < e1; e++) {
        int src = g_csr[e];
        float4 v = *(const float4*)(h + (size_t)src * F + f4 * 4);
        s.x += v.x; s.y += v.y; s.z += v.z; s.w += v.w;
    }
    float id = g_invdeg[node];
    s.x *= id; s.y *= id; s.z *= id; s.w *= id;
    *(float4*)(g_agg + (size_t)node * F + f4 * 4) = s;
}

// ---------------- MP GEMM: C = relu(A1@W1 + A2@W2 + bias), FFMA2 + ping-pong ----
#define BSTR 132

__global__ __launch_bounds__(256) void k_sgemm_dual(
    const float* __restrict__ A1, int K1,
    const float* __restrict__ A2, int K2,
    const float* __restrict__ W1, const float* __restrict__ W2,
    const float* __restrict__ bias,
    float* __restrict__ C, int M, int NC)
{
    __shared__ __align__(16) float As[2][8][BSTR];
    __shared__ __align__(16) float Bs[2][8][BSTR];
    int tid = threadIdx.x;
    int rowBlock = blockIdx.y * 128;
    int colBlock = blockIdx.x * 128;
    int tx = tid & 15, ty = tid >> 4;
    int rowBase = ty * 8, colBase = tx * 8;

    int la_m = tid >> 1;
    int la_k = (tid & 1) * 4;
    int lb_k = tid >> 5;
    int lb_n = (tid & 31) * 4;

    unsigned long long acc2[8][4];
#pragma unroll
    for (int i = 0; i < 8; i++)
#pragma unroll
        for (int j = 0; j < 4; j++) acc2[i][j] = 0ull;

    int nt1 = K1 >> 3;
    int nt = nt1 + (K2 >> 3);

    float4 av, bv;
    {
        int gm = rowBlock + la_m;
        av = (gm < M) ? *(const float4*)(A1 + (size_t)gm * K1 + la_k)
                      : make_float4(0.f, 0.f, 0.f, 0.f);
        bv = *(const float4*)(W1 + (size_t)lb_k * NC + colBlock + lb_n);
    }
    As[0][la_k + 0][la_m] = av.x;
    As[0][la_k + 1][la_m] = av.y;
    As[0][la_k + 2][la_m] = av.z;
    As[0][la_k + 3][la_m] = av.w;
    *(float4*)&Bs[0][lb_k][lb_n] = bv;
    __syncthreads();

    int s = 0;
#pragma unroll 1
    for (int t = 0; t < nt; t++) {
        if (t + 1 < nt) {
            int tn = t + 1;
            const float* A; const float* W; int K; int k0;
            if (tn < nt1) { A = A1; W = W1; K = K1; k0 = tn * 8; }
            else          { A = A2; W = W2; K = K2; k0 = (tn - nt1) * 8; }
            int gm = rowBlock + la_m;
            av = (gm < M) ? *(const float4*)(A + (size_t)gm * K + k0 + la_k)
                          : make_float4(0.f, 0.f, 0.f, 0.f);
            bv = *(const float4*)(W + (size_t)(k0 + lb_k) * NC + colBlock + lb_n);
        }
#pragma unroll
        for (int k = 0; k < 8; k++) {
            float4 a0 = *(const float4*)&As[s][k][rowBase];
            float4 a1 = *(const float4*)&As[s][k][rowBase + 4];
            float4 b0 = *(const float4*)&Bs[s][k][colBase];
            float4 b1 = *(const float4*)&Bs[s][k][colBase + 4];
            unsigned long long rbp[4];
            rbp[0] = pk2(b0.x, b0.y);
            rbp[1] = pk2(b0.z, b0.w);
            rbp[2] = pk2(b1.x, b1.y);
            rbp[3] = pk2(b1.z, b1.w);
            float ra[8] = {a0.x, a0.y, a0.z, a0.w, a1.x, a1.y, a1.z, a1.w};
#pragma unroll
            for (int i = 0; i < 8; i++) {
                unsigned long long rai = pk2(ra[i], ra[i]);
#pragma unroll
                for (int j = 0; j < 4; j++) FFMA2(acc2[i][j], rai, rbp[j]);
            }
        }
        if (t + 1 < nt) {
            int sn = s ^ 1;
            As[sn][la_k + 0][la_m] = av.x;
            As[sn][la_k + 1][la_m] = av.y;
            As[sn][la_k + 2][la_m] = av.z;
            As[sn][la_k + 3][la_m] = av.w;
            *(float4*)&Bs[sn][lb_k][lb_n] = bv;
        }
        __syncthreads();
        s ^= 1;
    }

    float4 bb0 = *(const float4*)(bias + colBlock + colBase);
    float4 bb1 = *(const float4*)(bias + colBlock + colBase + 4);
    float bbs[8] = {bb0.x, bb0.y, bb0.z, bb0.w, bb1.x, bb1.y, bb1.z, bb1.w};
#pragma unroll
    for (int i = 0; i < 8; i++) {
        int gm = rowBlock + rowBase + i;
        if (gm >= M) continue;
        float o[8];
#pragma unroll
        for (int j = 0; j < 4; j++) upk2(acc2[i][j], o[j * 2], o[j * 2 + 1]);
#pragma unroll
        for (int j = 0; j < 8; j++) o[j] = fmaxf(o[j] + bbs[j], 0.f);
        float* cp = C + (size_t)gm * NC + colBlock + colBase;
        *(float4*)cp       = make_float4(o[0], o[1], o[2], o[3]);
        *(float4*)(cp + 4) = make_float4(o[4], o[5], o[6], o[7]);
    }
}

// ---------------- fused decoder: 3 col-blocks per CTA, reg/SMEM logit accum ----
// One CTA owns 128 prediction rows exclusively: loops over the 3 col-blocks of
// Wd1, accumulates logit partials in persistent SMEM, then applies bd2 +
// log_softmax in-kernel. No atomics, no g_logit, no separate softmax launch.
__global__ __launch_bounds__(256) void k_gemm_dec(
    const float* __restrict__ Wd1, const float* __restrict__ bd1,
    const float* __restrict__ Wd2, const float* __restrict__ bd2,
    const int* __restrict__ place_idx, const int* __restrict__ src_idx,
    const int* __restrict__ t_idx)
{
    __shared__ __align__(16) float As[2][8][BSTR];
    __shared__ __align__(16) float Bs[2][8][BSTR];
    __shared__ __align__(16) float2 red[128][17];

    int tid = threadIdx.x;
    int rowBlock = blockIdx.x * 128;
    int tx = tid & 15, ty = tid >> 4;
    int rowBase = ty * 8, colBase = tx * 8;

    int la_m = tid >> 1;
    int la_k = (tid & 1) * 4;
    int lb_k = tid >> 5;
    int lb_n = (tid & 31) * 4;

    // zero persistent logit-partial array
#pragma unroll
    for (int i = tid; i < 128 * 17; i += 256)
        ((float2*)red)[i] = make_float2(0.f, 0.f);

    // per-thread gather bases for the row this thread loads
    int gm = rowBlock + la_m;
    bool mok = gm < PP;
    const float* aptr[3];
    {
        int pidx = mok ? gm : 0;
        int t = t_idx[pidx];
        aptr[0] = g_feats + ((size_t)t * NN + place_idx[pidx]) * HH;
        aptr[1] = g_feats + ((size_t)t * NN + src_idx[pidx]) * HH;
        aptr[2] = g_dstf + (size_t)pidx * HH;
    }

    const int nt = CATW / 8;  // 48 k-tiles per col-block

#pragma unroll 1
    for (int cb = 0; cb < 3; cb++) {
        int colBlock = cb * 128;

        unsigned long long acc2[8][4];
#pragma unroll
        for (int i = 0; i < 8; i++)
#pragma unroll
            for (int j = 0; j < 4; j++) acc2[i][j] = 0ull;

        float4 av, bv;
        av = mok ? *(const float4*)(aptr[0] + la_k) : make_float4(0.f, 0.f, 0.f, 0.f);
        bv = *(const float4*)(Wd1 + (size_t)lb_k * CATW + colBlock + lb_n);
        As[0][la_k + 0][la_m] = av.x;
        As[0][la_k + 1][la_m] = av.y;
        As[0][la_k + 2][la_m] = av.z;
        As[0][la_k + 3][la_m] = av.w;
        *(float4*)&Bs[0][lb_k][lb_n] = bv;
        __syncthreads();

        int s = 0;
#pragma unroll 1
        for (int t = 0; t < nt; t++) {
            if (t + 1 < nt) {
                int k0 = (t + 1) * 8;
                int seg = k0 >> 7, koff = k0 & 127;
                av = mok ? *(const float4*)(aptr[seg] + koff + la_k)
                         : make_float4(0.f, 0.f, 0.f, 0.f);
                bv = *(const float4*)(Wd1 + (size_t)(k0 + lb_k) * CATW + colBlock + lb_n);
            }
#pragma unroll
            for (int k = 0; k < 8; k++) {
                float4 a0 = *(const float4*)&As[s][k][rowBase];
                float4 a1 = *(const float4*)&As[s][k][rowBase + 4];
                float4 b0 = *(const float4*)&Bs[s][k][colBase];
                float4 b1 = *(const float4*)&Bs[s][k][colBase + 4];
                unsigned long long rbp[4];
                rbp[0] = pk2(b0.x, b0.y);
                rbp[1] = pk2(b0.z, b0.w);
                rbp[2] = pk2(b1.x, b1.y);
                rbp[3] = pk2(b1.z, b1.w);
                float ra[8] = {a0.x, a0.y, a0.z, a0.w, a1.x, a1.y, a1.z, a1.w};
#pragma unroll
                for (int i = 0; i < 8; i++) {
                    unsigned long long rai = pk2(ra[i], ra[i]);
#pragma unroll
                    for (int j = 0; j < 4; j++) FFMA2(acc2[i][j], rai, rbp[j]);
                }
            }
            if (t + 1 < nt) {
                int sn = s ^ 1;
                As[sn][la_k + 0][la_m] = av.x;
                As[sn][la_k + 1][la_m] = av.y;
                As[sn][la_k + 2][la_m] = av.z;
                As[sn][la_k + 3][la_m] = av.w;
                *(float4*)&Bs[sn][lb_k][lb_n] = bv;
            }
            __syncthreads();
            s ^= 1;
        }

        // partial epilogue for this col-block: relu(acc + bd1) @ Wd2 slice
        float4 bb0 = *(const float4*)(bd1 + colBlock + colBase);
        float4 bb1 = *(const float4*)(bd1 + colBlock + colBase + 4);
        float bbs[8] = {bb0.x, bb0.y, bb0.z, bb0.w, bb1.x, bb1.y, bb1.z, bb1.w};
        float w20[8], w21[8];
#pragma unroll
        for (int j = 0; j < 8; j++) {
            float2 w = *(const float2*)(Wd2 + (colBlock + colBase + j) * 2);
            w20[j] = w.x; w21[j] = w.y;
        }
#pragma unroll
        for (int i = 0; i < 8; i++) {
            float o[8];
#pragma unroll
            for (int j = 0; j < 4; j++) upk2(acc2[i][j], o[j * 2], o[j * 2 + 1]);
            float pa0 = 0.f, pa1 = 0.f;
#pragma unroll
            for (int j = 0; j < 8; j++) {
                float h = fmaxf(o[j] + bbs[j], 0.f);
                pa0 += h * w20[j];
                pa1 += h * w21[j];
            }
            float2 cur = red[rowBase + i][tx];
            red[rowBase + i][tx] = make_float2(cur.x + pa0, cur.y + pa1);
        }
        __syncthreads();
    }

    // final reduce + bd2 + log_softmax
    if (tid < 128) {
        int p = rowBlock + tid;
        if (p < PP) {
            float s0 = 0.f, s1 = 0.f;
#pragma unroll
            for (int c = 0; c < 16; c++) {
                float2 v = red[tid][c];
                s0 += v.x; s1 += v.y;
            }
            float a0 = s0 + bd2[0];
            float a1 = s1 + bd2[1];
            float m = fmaxf(a0, a1);
            float lse = m + logf(expf(a0 - m) + expf(a1 - m));
            g_logprob[p * 2]     = a0 - lse;
            g_logprob[p * 2 + 1] = a1 - lse;
        }
    }
}

// ---------------- dst segment-sum (atomic-free; dst_seg is sorted) ----------------
__global__ void k_dst_bounds(const int* __restrict__ dst_seg) {
    int p = blockIdx.x * blockDim.x + threadIdx.x;
    if (p > PP) return;
    int lo = 0, hi = DD;
    while (lo < hi) {
        int mid = (lo + hi) >> 1;
        if (dst_seg[mid] < p) lo = mid + 1; else hi = mid;
    }
    g_dstart[p] = lo;
}

__global__ void k_dst_sum(const int* __restrict__ dst_nodes, const int* __restrict__ t_idx) {
    int idx = blockIdx.x * blockDim.x + threadIdx.x;
    if (idx >= PP * 32) return;
    int p = idx >> 5, q = idx & 31;
    int e0 = g_dstart[p], e1 = g_dstart[p + 1];
    const float* base = g_feats + (size_t)t_idx[p] * NN * HH + q * 4;
    float4 s = make_float4(0.f, 0.f, 0.f, 0.f);
    for (int e = e0; e < e1; e++) {
        float4 v = *(const float4*)(base + (size_t)dst_nodes[e] * HH);
        s.x += v.x; s.y += v.y; s.z += v.z; s.w += v.w;
    }
    *(float4*)(g_dstf + (size_t)p * HH + q * 4) = s;
}

// ---------------- group / variant bookkeeping ----------------
__global__ void k_group_sum(const int* __restrict__ group_id) {
    int p = blockIdx.x * blockDim.x + threadIdx.x;
    if (p >= PP) return;
    int g = group_id[p];
    atomicAdd(&g_gsum[g * 2 + 0], (double)g_logprob[p * 2 + 0]);
    atomicAdd(&g_gsum[g * 2 + 1], (double)g_logprob[p * 2 + 1]);
}

__global__ void k_var_starts(const int* __restrict__ vg) {
    int g = blockIdx.x * blockDim.x + threadIdx.x;
    if (g >= GG) return;
    int v = vg[g];
    if (g == 0 || vg[g - 1] != v) g_vstart[v] = g;
}

__global__ void k_within(const int* __restrict__ vg) {
    int v = blockIdx.x * blockDim.x + threadIdx.x;
    if (v >= VV) return;
    int g = g_vstart[v];
    if (g < 0) return;
    double r0 = 0.0, r1 = 0.0;
    while (g < GG && vg[g] == v) {
        r0 += g_gsum[g * 2];
        r1 += g_gsum[g * 2 + 1];
        g_within[g * 2]     = (float)r0;
        g_within[g * 2 + 1] = (float)r1;
        g++;
    }
}

__global__ void k_logc(const float* __restrict__ counts) {
    __shared__ double red[8];
    double s = 0.0;
    for (int v = threadIdx.x; v < VV; v += blockDim.x) s += (double)counts[v];
#pragma unroll
    for (int o = 16; o; o >>= 1) s += __shfl_down_sync(0xffffffffu, s, o);
    if ((threadIdx.x & 31) == 0) red[threadIdx.x >> 5] = s;
    __syncthreads();
    double tot = 0.0;
#pragma unroll
    for (int i = 0; i < 8; i++) tot += red[i];
    for (int v = threadIdx.x; v < VV; v += blockDim.x)
        g_logc[v] = logf((float)((double)counts[v] / tot));
}

__global__ void k_finalize(const int* __restrict__ group_id, const int* __restrict__ vg,
                           const int* __restrict__ place_idx, float* __restrict__ out) {
    int idx = blockIdx.x * blockDim.x + threadIdx.x;
    if (idx >= PP * 2) return;
    int p = idx >> 1, o = idx & 1;
    int g = group_id[p];
    float add = g_logprob[idx] + g_within[g * 2 + o] + g_logc[vg[g]];
    atomicAdd(&out[place_idx[p] * 2 + o], add);
}

// ---------------- host launch ----------------
extern "C" void kernel_launch(void* const* d_in, const int* in_sizes, int n_in,
                              void* d_out, int out_size) {
    const float* x      = (const float*)d_in[0];
    const float* Wes    = (const float*)d_in[1];
    const float* Wen    = (const float*)d_in[2];
    const float* benc   = (const float*)d_in[3];
    const float* W2s    = (const float*)d_in[4];
    const float* W2n    = (const float*)d_in[5];
    const float* b2     = (const float*)d_in[6];
    const float* Wd1    = (const float*)d_in[7];
    const float* bd1    = (const float*)d_in[8];
    const float* Wd2    = (const float*)d_in[9];
    const float* bd2    = (const float*)d_in[10];
    const float* counts = (const float*)d_in[11];
    const int* edge_src = (const int*)d_in[12];
    const int* edge_dst = (const int*)d_in[13];
    const int* place_idx = (const int*)d_in[14];
    const int* src_idx   = (const int*)d_in[15];
    const int* t_idx     = (const int*)d_in[16];
    const int* dst_nodes = (const int*)d_in[17];
    const int* dst_seg   = (const int*)d_in[18];
    const int* group_id  = (const int*)d_in[19];
    const int* vg        = (const int*)d_in[20];
    float* out = (float*)d_out;

    void *p_deg, *p_gsum, *p_vstart, *p_feats, *p_agg;
    cudaGetSymbolAddress(&p_deg, g_deg);
    cudaGetSymbolAddress(&p_gsum, g_gsum);
    cudaGetSymbolAddress(&p_vstart, g_vstart);
    cudaGetSymbolAddress(&p_feats, g_feats);
    cudaGetSymbolAddress(&p_agg, g_agg);
    float* feats = (float*)p_feats;
    float* agg   = (float*)p_agg;

    // --- CSR build ---
    cudaMemsetAsync(p_deg, 0, NN * sizeof(int));
    k_count_deg<<<(EE + 255) / 256, 256>>>(edge_dst);
    k_scan<<<1, 1024>>>();
    k_fill<<<(EE + 255) / 256, 256>>>(edge_src, edge_dst);

    dim3 gemmGridN(1, (NN + 127) / 128);

    // --- encoder ---
    k_aggregate4<FINF><<<(NN + 15) / 16, dim3(16, 16)>>>(x);
    k_sgemm_dual<<<gemmGridN, 256>>>(x, FINF, agg, FINF, Wes, Wen, benc,
                                     feats, NN, HH);

    // --- T recurrent steps ---
    for (int t = 1; t <= TT; t++) {
        const float* hp = feats + (size_t)(t - 1) * NN * HH;
        float* hn = feats + (size_t)t * NN * HH;
        k_aggregate4<HH><<<(NN + 7) / 8, dim3(32, 8)>>>(hp);
        k_sgemm_dual<<<gemmGridN, 256>>>(hp, HH, agg, HH, W2s, W2n, b2,
                                         hn, NN, HH);
    }

    // --- dst segment sums ---
    k_dst_bounds<<<(PP + 256) / 256, 256>>>(dst_seg);
    k_dst_sum<<<(PP * 32 + 255) / 256, 256>>>(dst_nodes, t_idx);

    // --- fused decoder GEMM (3 col-blocks/CTA) + logits + log_softmax ---
    k_gemm_dec<<<(PP + 127) / 128, 256>>>(Wd1, bd1, Wd2, bd2,
                                          place_idx, src_idx, t_idx);

    // --- group / variant running sums ---
    cudaMemsetAsync(p_gsum, 0, GG * 2 * sizeof(double));
    cudaMemsetAsync(p_vstart, 0xFF, VV * sizeof(int));
    k_group_sum<<<(PP + 255) / 256, 256>>>(group_id);
    k_var_starts<<<(GG + 255) / 256, 256>>>(vg);
    k_logc<<<1, 256>>>(counts);
    k_within<<<(VV + 255) / 256, 256>>>(vg);

    // --- output scatter ---
    cudaMemsetAsync(d_out, 0, (size_t)out_size * sizeof(float));
    k_finalize<<<(PP * 2 + 255) / 256, 256>>>(group_id, vg, place_idx, out);
}